// round 10
// baseline (speedup 1.0000x reference)
#include <cuda_runtime.h>

// ODEFunc: 4 x { Y = X @ A^T (V-mix) ; Z = w @ Y + b (C-GEMM) ; X = relu(Z + X) }
// N=64, C=256, T=64, V=25.  One block per (n,t); whole recurrence in SMEM.
// Round 10: packed fma.rn.f32x2 everywhere + float4 w-tile reads (stride 36).

#define N_ 64
#define C_ 256
#define T_ 64
#define V_ 25
#define VP 28          // padded V (float4-aligned Y rows)
#define WSTR 36        // w tile row stride in floats (mult of 4; 36 -> 4i bank walk, conflict-free LDS.128)
#define CHUNK 32       // c-columns of w staged per pass

// dynamic smem partition (floats)
#define XS_OFF 0
#define XS_LEN (C_ * V_)            // 6400
#define AS_OFF (XS_OFF + XS_LEN)
#define AS_LEN (V_ * VP)            // 700
#define WS_OFF (AS_OFF + AS_LEN)
#define WS_LEN (C_ * WSTR)          // 9216
#define YS_OFF (WS_OFF + WS_LEN)
#define YS_LEN (C_ * VP + 8)        // 7176 (pad so row-overrun reads stay in-bounds)
#define SMEM_FLOATS (YS_OFF + YS_LEN)
#define SMEM_BYTES  (SMEM_FLOATS * 4)

typedef unsigned long long u64;

__device__ __forceinline__ u64 pack2(float lo, float hi) {
    u64 r; asm("mov.b64 %0, {%1, %2};" : "=l"(r) : "f"(lo), "f"(hi)); return r;
}
__device__ __forceinline__ u64 dup2(float s) {
    u64 r; asm("mov.b64 %0, {%1, %1};" : "=l"(r) : "f"(s)); return r;
}
__device__ __forceinline__ float2 unpack2(u64 a) {
    float2 r; asm("mov.b64 {%0, %1}, %2;" : "=f"(r.x), "=f"(r.y) : "l"(a)); return r;
}
__device__ __forceinline__ void fma2(u64& d, u64 a, u64 b) {
    asm("fma.rn.f32x2 %0, %1, %2, %0;" : "+l"(d) : "l"(a), "l"(b));
}

__global__ __launch_bounds__(256, 2)
void odefunc_kernel(const float* __restrict__ x,
                    const float* __restrict__ A,
                    const float* __restrict__ w1, const float* __restrict__ b1,
                    const float* __restrict__ w2, const float* __restrict__ b2,
                    const float* __restrict__ w3, const float* __restrict__ b3,
                    const float* __restrict__ w4, const float* __restrict__ b4,
                    float* __restrict__ out)
{
    extern __shared__ float smem[];
    float* Xs = smem + XS_OFF;   // [C][25]   stride 25 (odd -> conflict-free scalar)
    float* As = smem + AS_OFF;   // [25][VP]  zero-padded cols 25..27
    float* Ws = smem + WS_OFF;   // [C][WSTR] w chunk, float4-accessed
    float* Ys = smem + YS_OFF;   // [C][VP]   zero-padded cols 25..27

    const int tid = threadIdx.x;
    const int pos = blockIdx.x;          // 0..4095
    const int n = pos >> 6;
    const int t = pos & 63;
    const int base = (n * (C_ * T_) + t) * V_;   // (n, 0, t, 0); channel stride = T_*V_

    // ---- load A (padded) ----
    for (int i = tid; i < V_ * VP; i += 256) {
        int v = i / VP, u = i - v * VP;
        As[i] = (u < V_) ? A[v * V_ + u] : 0.0f;
    }

    // ---- load X tile: thread = channel row ----
    {
        const float* xp = x + base + tid * (T_ * V_);
        #pragma unroll
        for (int v = 0; v < V_; v++) Xs[tid * V_ + v] = xp[v];
    }

    const float* wptr[4] = { w1, w2, w3, w4 };
    const float* bptr[4] = { b1, b2, b3, b4 };

    // stage-B thread mapping: og = output-channel base, vg = v-group (warp-uniform)
    const int og = tid & 63;
    const int vg = tid >> 6;
    const int v0 = vg * 8;               // v-groups: [0,8) [8,16) [16,24) [24,28)

    for (int layer = 0; layer < 4; layer++) {
        const float* __restrict__ w = wptr[layer];
        const float* __restrict__ b = bptr[layer];

        __syncthreads();   // X ready (initial load or previous epilogue)

        // ---------- stage A: Y[c][v] = sum_u X[c][u] * A[v][u]  (thread = c) ----------
        {
            u64 xp2[14];                           // u pairs (0,1)..(26,27), pads zero
            const float* xrow = &Xs[tid * V_];
            #pragma unroll
            for (int k = 0; k < 12; k++) xp2[k] = pack2(xrow[2 * k], xrow[2 * k + 1]);
            xp2[12] = pack2(xrow[24], 0.0f);
            xp2[13] = 0ull;

            #pragma unroll
            for (int v = 0; v < V_; v++) {
                u64 acc0 = 0ull, acc1 = 0ull;
                #pragma unroll
                for (int k = 0; k < 7; k++) {      // 4 u's per step (broadcast LDS.128)
                    ulonglong2 a2 = *reinterpret_cast<const ulonglong2*>(&As[v * VP + 4 * k]);
                    fma2(acc0, xp2[2 * k],     a2.x);
                    fma2(acc1, xp2[2 * k + 1], a2.y);
                }
                float2 s0 = unpack2(acc0);
                float2 s1 = unpack2(acc1);
                Ys[tid * VP + v] = (s0.x + s0.y) + (s1.x + s1.y);
            }
            #pragma unroll
            for (int v = V_; v < VP; v++) Ys[tid * VP + v] = 0.0f;
        }

        // ---------- stage B: Z[o][v] = b[o] + sum_c w[o][c] * Y[c][v] ----------
        u64 acc[4][4];                              // 4 rows x 4 v-pairs
        #pragma unroll
        for (int r = 0; r < 4; r++) {
            u64 bd = dup2(b[og + r * 64]);
            #pragma unroll
            for (int j = 0; j < 4; j++) acc[r][j] = bd;
        }

        for (int c0 = 0; c0 < C_; c0 += CHUNK) {
            __syncthreads();   // previous chunk fully consumed
            // cooperative load: 256 rows x 32 cols, 8 float4 per thread (coalesced)
            #pragma unroll
            for (int k = 0; k < 8; k++) {
                int i = tid + k * 256;
                int o = i >> 3;
                int q = i & 7;
                *reinterpret_cast<float4*>(&Ws[o * WSTR + q * 4]) =
                    *reinterpret_cast<const float4*>(&w[o * C_ + c0 + q * 4]);
            }
            __syncthreads();   // chunk visible

            #pragma unroll
            for (int cc = 0; cc < CHUNK; cc += 4) {
                // 4 conflict-free LDS.128: w for 4 rows x 4 c's
                float4 wr0 = *reinterpret_cast<const float4*>(&Ws[(og      ) * WSTR + cc]);
                float4 wr1 = *reinterpret_cast<const float4*>(&Ws[(og +  64) * WSTR + cc]);
                float4 wr2 = *reinterpret_cast<const float4*>(&Ws[(og + 128) * WSTR + cc]);
                float4 wr3 = *reinterpret_cast<const float4*>(&Ws[(og + 192) * WSTR + cc]);

                #pragma unroll
                for (int c = 0; c < 4; c++) {
                    const float* yr = &Ys[(c0 + cc + c) * VP + v0];
                    ulonglong2 p0 = *reinterpret_cast<const ulonglong2*>(yr);       // v0..v3
                    float s0 = (c == 0) ? wr0.x : (c == 1) ? wr0.y : (c == 2) ? wr0.z : wr0.w;
                    float s1 = (c == 0) ? wr1.x : (c == 1) ? wr1.y : (c == 2) ? wr1.z : wr1.w;
                    float s2 = (c == 0) ? wr2.x : (c == 1) ? wr2.y : (c == 2) ? wr2.z : wr2.w;
                    float s3 = (c == 0) ? wr3.x : (c == 1) ? wr3.y : (c == 2) ? wr3.z : wr3.w;
                    u64 d0 = dup2(s0), d1 = dup2(s1), d2 = dup2(s2), d3 = dup2(s3);

                    fma2(acc[0][0], d0, p0.x);  fma2(acc[0][1], d0, p0.y);
                    fma2(acc[1][0], d1, p0.x);  fma2(acc[1][1], d1, p0.y);
                    fma2(acc[2][0], d2, p0.x);  fma2(acc[2][1], d2, p0.y);
                    fma2(acc[3][0], d3, p0.x);  fma2(acc[3][1], d3, p0.y);

                    if (vg != 3) {   // warp-uniform: groups 0-2 carry 8 v's
                        ulonglong2 p1 = *reinterpret_cast<const ulonglong2*>(yr + 4);  // v4..v7
                        fma2(acc[0][2], d0, p1.x);  fma2(acc[0][3], d0, p1.y);
                        fma2(acc[1][2], d1, p1.x);  fma2(acc[1][3], d1, p1.y);
                        fma2(acc[2][2], d2, p1.x);  fma2(acc[2][3], d2, p1.y);
                        fma2(acc[3][2], d3, p1.x);  fma2(acc[3][3], d3, p1.y);
                    }
                }
            }
        }

        __syncthreads();   // all stage-B reads of Ys/Ws done before X is rewritten

        // ---------- epilogue: X = relu(Z + X), in place ----------
        #pragma unroll
        for (int r = 0; r < 4; r++) {
            int o = og + r * 64;
            #pragma unroll
            for (int j = 0; j < 4; j++) {
                int v = v0 + 2 * j;
                if (v < V_) {
                    float2 z = unpack2(acc[r][j]);
                    Xs[o * V_ + v] = fmaxf(z.x + Xs[o * V_ + v], 0.0f);
                    if (v + 1 < V_)
                        Xs[o * V_ + v + 1] = fmaxf(z.y + Xs[o * V_ + v + 1], 0.0f);
                }
            }
        }
    }

    __syncthreads();
    // ---- store result: thread = channel row ----
    {
        float* op = out + base + tid * (T_ * V_);
        #pragma unroll
        for (int v = 0; v < V_; v++) op[v] = Xs[tid * V_ + v];
    }
}

extern "C" void kernel_launch(void* const* d_in, const int* in_sizes, int n_in,
                              void* d_out, int out_size)
{
    // inputs (metadata order): t, x, A, w1, b1, w2, b2, w3, b3, w4, b4
    const float* x  = (const float*)d_in[1];
    const float* A  = (const float*)d_in[2];
    const float* w1 = (const float*)d_in[3];
    const float* b1 = (const float*)d_in[4];
    const float* w2 = (const float*)d_in[5];
    const float* b2 = (const float*)d_in[6];
    const float* w3 = (const float*)d_in[7];
    const float* b3 = (const float*)d_in[8];
    const float* w4 = (const float*)d_in[9];
    const float* b4 = (const float*)d_in[10];
    float* out = (float*)d_out;

    cudaFuncSetAttribute(odefunc_kernel,
                         cudaFuncAttributeMaxDynamicSharedMemorySize, SMEM_BYTES);

    odefunc_kernel<<<N_ * T_, 256, SMEM_BYTES>>>(
        x, A, w1, b1, w2, b2, w3, b3, w4, b4, out);
}

// round 11
// speedup vs baseline: 1.0008x; 1.0008x over previous
#include <cuda_runtime.h>

// ODEFunc: 4 x { Y = X @ A^T (V-mix) ; Z = w @ Y + b (C-GEMM) ; X = relu(Z + X) }
// N=64, C=256, T=64, V=25.  One block per (n,t); whole recurrence in SMEM.
// Round 10: packed fma.rn.f32x2 everywhere + float4 w-tile reads (stride 36).

#define N_ 64
#define C_ 256
#define T_ 64
#define V_ 25
#define VP 28          // padded V (float4-aligned Y rows)
#define WSTR 36        // w tile row stride in floats (mult of 4; 36 -> 4i bank walk, conflict-free LDS.128)
#define CHUNK 32       // c-columns of w staged per pass

// dynamic smem partition (floats)
#define XS_OFF 0
#define XS_LEN (C_ * V_)            // 6400
#define AS_OFF (XS_OFF + XS_LEN)
#define AS_LEN (V_ * VP)            // 700
#define WS_OFF (AS_OFF + AS_LEN)
#define WS_LEN (C_ * WSTR)          // 9216
#define YS_OFF (WS_OFF + WS_LEN)
#define YS_LEN (C_ * VP + 8)        // 7176 (pad so row-overrun reads stay in-bounds)
#define SMEM_FLOATS (YS_OFF + YS_LEN)
#define SMEM_BYTES  (SMEM_FLOATS * 4)

typedef unsigned long long u64;

__device__ __forceinline__ u64 pack2(float lo, float hi) {
    u64 r; asm("mov.b64 %0, {%1, %2};" : "=l"(r) : "f"(lo), "f"(hi)); return r;
}
__device__ __forceinline__ u64 dup2(float s) {
    u64 r; asm("mov.b64 %0, {%1, %1};" : "=l"(r) : "f"(s)); return r;
}
__device__ __forceinline__ float2 unpack2(u64 a) {
    float2 r; asm("mov.b64 {%0, %1}, %2;" : "=f"(r.x), "=f"(r.y) : "l"(a)); return r;
}
__device__ __forceinline__ void fma2(u64& d, u64 a, u64 b) {
    asm("fma.rn.f32x2 %0, %1, %2, %0;" : "+l"(d) : "l"(a), "l"(b));
}

__global__ __launch_bounds__(256, 2)
void odefunc_kernel(const float* __restrict__ x,
                    const float* __restrict__ A,
                    const float* __restrict__ w1, const float* __restrict__ b1,
                    const float* __restrict__ w2, const float* __restrict__ b2,
                    const float* __restrict__ w3, const float* __restrict__ b3,
                    const float* __restrict__ w4, const float* __restrict__ b4,
                    float* __restrict__ out)
{
    extern __shared__ float smem[];
    float* Xs = smem + XS_OFF;   // [C][25]   stride 25 (odd -> conflict-free scalar)
    float* As = smem + AS_OFF;   // [25][VP]  zero-padded cols 25..27
    float* Ws = smem + WS_OFF;   // [C][WSTR] w chunk, float4-accessed
    float* Ys = smem + YS_OFF;   // [C][VP]   zero-padded cols 25..27

    const int tid = threadIdx.x;
    const int pos = blockIdx.x;          // 0..4095
    const int n = pos >> 6;
    const int t = pos & 63;
    const int base = (n * (C_ * T_) + t) * V_;   // (n, 0, t, 0); channel stride = T_*V_

    // ---- load A (padded) ----
    for (int i = tid; i < V_ * VP; i += 256) {
        int v = i / VP, u = i - v * VP;
        As[i] = (u < V_) ? A[v * V_ + u] : 0.0f;
    }

    // ---- load X tile: thread = channel row ----
    {
        const float* xp = x + base + tid * (T_ * V_);
        #pragma unroll
        for (int v = 0; v < V_; v++) Xs[tid * V_ + v] = xp[v];
    }

    const float* wptr[4] = { w1, w2, w3, w4 };
    const float* bptr[4] = { b1, b2, b3, b4 };

    // stage-B thread mapping: og = output-channel base, vg = v-group (warp-uniform)
    const int og = tid & 63;
    const int vg = tid >> 6;
    const int v0 = vg * 8;               // v-groups: [0,8) [8,16) [16,24) [24,28)

    for (int layer = 0; layer < 4; layer++) {
        const float* __restrict__ w = wptr[layer];
        const float* __restrict__ b = bptr[layer];

        __syncthreads();   // X ready (initial load or previous epilogue)

        // ---------- stage A: Y[c][v] = sum_u X[c][u] * A[v][u]  (thread = c) ----------
        {
            u64 xp2[14];                           // u pairs (0,1)..(26,27), pads zero
            const float* xrow = &Xs[tid * V_];
            #pragma unroll
            for (int k = 0; k < 12; k++) xp2[k] = pack2(xrow[2 * k], xrow[2 * k + 1]);
            xp2[12] = pack2(xrow[24], 0.0f);
            xp2[13] = 0ull;

            #pragma unroll
            for (int v = 0; v < V_; v++) {
                u64 acc0 = 0ull, acc1 = 0ull;
                #pragma unroll
                for (int k = 0; k < 7; k++) {      // 4 u's per step (broadcast LDS.128)
                    ulonglong2 a2 = *reinterpret_cast<const ulonglong2*>(&As[v * VP + 4 * k]);
                    fma2(acc0, xp2[2 * k],     a2.x);
                    fma2(acc1, xp2[2 * k + 1], a2.y);
                }
                float2 s0 = unpack2(acc0);
                float2 s1 = unpack2(acc1);
                Ys[tid * VP + v] = (s0.x + s0.y) + (s1.x + s1.y);
            }
            #pragma unroll
            for (int v = V_; v < VP; v++) Ys[tid * VP + v] = 0.0f;
        }

        // ---------- stage B: Z[o][v] = b[o] + sum_c w[o][c] * Y[c][v] ----------
        u64 acc[4][4];                              // 4 rows x 4 v-pairs
        #pragma unroll
        for (int r = 0; r < 4; r++) {
            u64 bd = dup2(b[og + r * 64]);
            #pragma unroll
            for (int j = 0; j < 4; j++) acc[r][j] = bd;
        }

        for (int c0 = 0; c0 < C_; c0 += CHUNK) {
            __syncthreads();   // previous chunk fully consumed
            // cooperative load: 256 rows x 32 cols, 8 float4 per thread (coalesced)
            #pragma unroll
            for (int k = 0; k < 8; k++) {
                int i = tid + k * 256;
                int o = i >> 3;
                int q = i & 7;
                *reinterpret_cast<float4*>(&Ws[o * WSTR + q * 4]) =
                    *reinterpret_cast<const float4*>(&w[o * C_ + c0 + q * 4]);
            }
            __syncthreads();   // chunk visible

            #pragma unroll
            for (int cc = 0; cc < CHUNK; cc += 4) {
                // 4 conflict-free LDS.128: w for 4 rows x 4 c's
                float4 wr0 = *reinterpret_cast<const float4*>(&Ws[(og      ) * WSTR + cc]);
                float4 wr1 = *reinterpret_cast<const float4*>(&Ws[(og +  64) * WSTR + cc]);
                float4 wr2 = *reinterpret_cast<const float4*>(&Ws[(og + 128) * WSTR + cc]);
                float4 wr3 = *reinterpret_cast<const float4*>(&Ws[(og + 192) * WSTR + cc]);

                #pragma unroll
                for (int c = 0; c < 4; c++) {
                    const float* yr = &Ys[(c0 + cc + c) * VP + v0];
                    ulonglong2 p0 = *reinterpret_cast<const ulonglong2*>(yr);       // v0..v3
                    float s0 = (c == 0) ? wr0.x : (c == 1) ? wr0.y : (c == 2) ? wr0.z : wr0.w;
                    float s1 = (c == 0) ? wr1.x : (c == 1) ? wr1.y : (c == 2) ? wr1.z : wr1.w;
                    float s2 = (c == 0) ? wr2.x : (c == 1) ? wr2.y : (c == 2) ? wr2.z : wr2.w;
                    float s3 = (c == 0) ? wr3.x : (c == 1) ? wr3.y : (c == 2) ? wr3.z : wr3.w;
                    u64 d0 = dup2(s0), d1 = dup2(s1), d2 = dup2(s2), d3 = dup2(s3);

                    fma2(acc[0][0], d0, p0.x);  fma2(acc[0][1], d0, p0.y);
                    fma2(acc[1][0], d1, p0.x);  fma2(acc[1][1], d1, p0.y);
                    fma2(acc[2][0], d2, p0.x);  fma2(acc[2][1], d2, p0.y);
                    fma2(acc[3][0], d3, p0.x);  fma2(acc[3][1], d3, p0.y);

                    if (vg != 3) {   // warp-uniform: groups 0-2 carry 8 v's
                        ulonglong2 p1 = *reinterpret_cast<const ulonglong2*>(yr + 4);  // v4..v7
                        fma2(acc[0][2], d0, p1.x);  fma2(acc[0][3], d0, p1.y);
                        fma2(acc[1][2], d1, p1.x);  fma2(acc[1][3], d1, p1.y);
                        fma2(acc[2][2], d2, p1.x);  fma2(acc[2][3], d2, p1.y);
                        fma2(acc[3][2], d3, p1.x);  fma2(acc[3][3], d3, p1.y);
                    }
                }
            }
        }

        __syncthreads();   // all stage-B reads of Ys/Ws done before X is rewritten

        // ---------- epilogue: X = relu(Z + X), in place ----------
        #pragma unroll
        for (int r = 0; r < 4; r++) {
            int o = og + r * 64;
            #pragma unroll
            for (int j = 0; j < 4; j++) {
                int v = v0 + 2 * j;
                if (v < V_) {
                    float2 z = unpack2(acc[r][j]);
                    Xs[o * V_ + v] = fmaxf(z.x + Xs[o * V_ + v], 0.0f);
                    if (v + 1 < V_)
                        Xs[o * V_ + v + 1] = fmaxf(z.y + Xs[o * V_ + v + 1], 0.0f);
                }
            }
        }
    }

    __syncthreads();
    // ---- store result: thread = channel row ----
    {
        float* op = out + base + tid * (T_ * V_);
        #pragma unroll
        for (int v = 0; v < V_; v++) op[v] = Xs[tid * V_ + v];
    }
}

extern "C" void kernel_launch(void* const* d_in, const int* in_sizes, int n_in,
                              void* d_out, int out_size)
{
    // inputs (metadata order): t, x, A, w1, b1, w2, b2, w3, b3, w4, b4
    const float* x  = (const float*)d_in[1];
    const float* A  = (const float*)d_in[2];
    const float* w1 = (const float*)d_in[3];
    const float* b1 = (const float*)d_in[4];
    const float* w2 = (const float*)d_in[5];
    const float* b2 = (const float*)d_in[6];
    const float* w3 = (const float*)d_in[7];
    const float* b3 = (const float*)d_in[8];
    const float* w4 = (const float*)d_in[9];
    const float* b4 = (const float*)d_in[10];
    float* out = (float*)d_out;

    cudaFuncSetAttribute(odefunc_kernel,
                         cudaFuncAttributeMaxDynamicSharedMemorySize, SMEM_BYTES);

    odefunc_kernel<<<N_ * T_, 256, SMEM_BYTES>>>(
        x, A, w1, b1, w2, b2, w3, b3, w4, b4, out);
}